// round 14
// baseline (speedup 1.0000x reference)
#include <cuda_runtime.h>
#include <stdint.h>
#include <stddef.h>
#include <math.h>

#define BATCH 2
#define TLEN  2048
#define DM    1024
#define NH    16
#define DHD   64
#define BT    (BATCH * TLEN)   // 4096

// perm8: k-columns permuted per 8-group as [0,4,1,5,2,6,3,7]
// s(j) = j<4 ? 2j : 2j-7.  Pair (t, t+4) -> slots (2t, 2t+1): one LDS.64.

// ---------------------------------------------------------------------------
// Scratch
// ---------------------------------------------------------------------------
__device__ float g_q[BT * DM];    // perm8 on d (per head)
__device__ float g_k[BT * DM];    // perm8 on d
__device__ float g_v[BT * DM];    // normal d
__device__ float g_ot[BT * DM];   // perm8 on d (feeds out-proj)
__device__ float g_xc[BT * DM];   // perm8 on k
__device__ float g_wq[DM * DM];   // perm8 on k
__device__ float g_wk[DM * DM];
__device__ float g_wv[DM * DM];
__device__ float g_wo[DM * DM];   // perm8 on k

// ---------------------------------------------------------------------------
// Helpers
// ---------------------------------------------------------------------------
__device__ __forceinline__ float f2tf32(float x) {
    uint32_t u;
    asm("cvt.rna.tf32.f32 %0, %1;" : "=r"(u) : "f"(x));
    return __uint_as_float(u);
}
__device__ __forceinline__ float ex2(float x) {
    float r;
    asm("ex2.approx.f32 %0, %1;" : "=f"(r) : "f"(x));
    return r;
}
__device__ __forceinline__ void cp16(uint32_t smem, const void* gmem) {
    asm volatile("cp.async.cg.shared.global [%0], [%1], 16;"
                 :: "r"(smem), "l"(gmem));
}
#define CP_COMMIT() asm volatile("cp.async.commit_group;")
#define CP_WAIT0()  asm volatile("cp.async.wait_group 0;")
#define CP_WAIT1()  asm volatile("cp.async.wait_group 1;")

#define MMA_TF32(d, a, b)                                                   \
    asm volatile(                                                           \
        "mma.sync.aligned.m16n8k8.row.col.f32.tf32.tf32.f32 "               \
        "{%0,%1,%2,%3},{%4,%5,%6,%7},{%8,%9},{%0,%1,%2,%3};"                \
        : "+f"((d)[0]), "+f"((d)[1]), "+f"((d)[2]), "+f"((d)[3])            \
        : "r"((a)[0]), "r"((a)[1]), "r"((a)[2]), "r"((a)[3]),               \
          "r"((b)[0]), "r"((b)[1]))

// ---------------------------------------------------------------------------
// cvt: fp32 -> tf32 (RN) with perm8 on columns.  Processes one 8-group
// (two float4) per thread: out0=(c0,c4,c1,c5), out1=(c2,c6,c3,c7).
// ---------------------------------------------------------------------------
__device__ __forceinline__ void cvt_perm8(const float4* in, float4* out, int i) {
    float4 f0 = in[2 * i], f1 = in[2 * i + 1];
    float4 o0 = make_float4(f2tf32(f0.x), f2tf32(f1.x), f2tf32(f0.y), f2tf32(f1.y));
    float4 o1 = make_float4(f2tf32(f0.z), f2tf32(f1.z), f2tf32(f0.w), f2tf32(f1.w));
    out[2 * i]     = o0;
    out[2 * i + 1] = o1;
}

__global__ void cvt_x(const float4* __restrict__ in, float4* __restrict__ out, int n8) {
    int i = blockIdx.x * blockDim.x + threadIdx.x;
    if (i < n8) cvt_perm8(in, out, i);
}

__global__ void cvt_w4(const float4* __restrict__ i0, float4* __restrict__ o0,
                       const float4* __restrict__ i1, float4* __restrict__ o1,
                       const float4* __restrict__ i2, float4* __restrict__ o2,
                       const float4* __restrict__ i3, float4* __restrict__ o3,
                       int n8) {
    const float4* in = i0; float4* out = o0;
    if (blockIdx.z == 1) { in = i1; out = o1; }
    else if (blockIdx.z == 2) { in = i2; out = o2; }
    else if (blockIdx.z == 3) { in = i3; out = o3; }
    int i = blockIdx.x * blockDim.x + threadIdx.x;
    if (i < n8) cvt_perm8(in, out, i);
}

// ---------------------------------------------------------------------------
// tf32 GEMM (NT), perm8 k-layout: fragment loads are LDS.64.
// 256 threads (8 warps 2x4 of 64x64), tile 128x256, BK=32, double-buffered.
// QKV: z selects (B,C); z=0,1 (q,k) epilogues write perm8 d; z=2 (v) normal.
// ---------------------------------------------------------------------------
#define GS    40                       // ≡8 mod 32 -> conflict-free LDS.64
#define ABUF  (128 * GS)
#define BBUF  (256 * GS)
#define GEMM_SMEM ((2 * ABUF + 2 * BBUF) * 4)   // 122880

template <bool QKV>
__global__ __launch_bounds__(256)
void gemm_tf32(const float* __restrict__ A,
               const float* __restrict__ B0, const float* __restrict__ B1,
               const float* __restrict__ B2,
               float* __restrict__ C0, float* __restrict__ C1,
               float* __restrict__ C2,
               int M, int N, int K)
{
    const float* B = B0;
    float* C = C0;
    if (QKV) {
        if (blockIdx.z == 1) { B = B1; C = C1; }
        else if (blockIdx.z == 2) { B = B2; C = C2; }
    }

    extern __shared__ float sm[];
    float* As = sm;
    float* Bs = sm + 2 * ABUF;

    const int tid  = threadIdx.x;
    const int lane = tid & 31;
    const int warp = tid >> 5;
    const int g    = lane >> 2;
    const int t    = lane & 3;
    const int m0   = blockIdx.y * 128;
    const int n0   = blockIdx.x * 256;
    const int mw   = (warp >> 2) * 64;
    const int nw   = (warp & 3) * 64;

    const int lr = tid >> 3;               // 0..31
    const int lc = (tid & 7) << 2;         // 0..28
    const float* Ag = A + (size_t)(m0 + lr) * K + lc;
    const float* Bg = B + (size_t)(n0 + lr) * K + lc;

    const uint32_t sA = (uint32_t)__cvta_generic_to_shared(As);
    const uint32_t sB = (uint32_t)__cvta_generic_to_shared(Bs);
    const uint32_t soff = (uint32_t)(lr * GS + lc) * 4u;

    float acc[4][8][4];
#pragma unroll
    for (int mt = 0; mt < 4; mt++)
#pragma unroll
        for (int nt = 0; nt < 8; nt++)
#pragma unroll
            for (int r = 0; r < 4; r++) acc[mt][nt][r] = 0.0f;

    const int nkt = K >> 5;

#pragma unroll
    for (int i = 0; i < 4; i++)
        cp16(sA + soff + (uint32_t)(i * 32 * GS * 4), Ag + (size_t)i * 32 * K);
#pragma unroll
    for (int i = 0; i < 8; i++)
        cp16(sB + soff + (uint32_t)(i * 32 * GS * 4), Bg + (size_t)i * 32 * K);
    CP_COMMIT();

    for (int kt = 0; kt < nkt; kt++) {
        const int cur = kt & 1;
        if (kt + 1 < nkt) {
            const int nxt = cur ^ 1;
            const float* Ap = Ag + (size_t)(kt + 1) * 32;
            const float* Bp = Bg + (size_t)(kt + 1) * 32;
            const uint32_t ao = (uint32_t)(nxt * ABUF) * 4u;
            const uint32_t bo = (uint32_t)(nxt * BBUF) * 4u;
#pragma unroll
            for (int i = 0; i < 4; i++)
                cp16(sA + ao + soff + (uint32_t)(i * 32 * GS * 4), Ap + (size_t)i * 32 * K);
#pragma unroll
            for (int i = 0; i < 8; i++)
                cp16(sB + bo + soff + (uint32_t)(i * 32 * GS * 4), Bp + (size_t)i * 32 * K);
            CP_COMMIT();
            CP_WAIT1();
        } else {
            CP_WAIT0();
        }
        __syncthreads();

        const float* Ab = As + cur * ABUF + mw * GS;
        const float* Bb = Bs + cur * BBUF + nw * GS;
#pragma unroll
        for (int kc = 0; kc < 4; kc++) {
            const int kk = kc * 8;
            uint32_t af[4][4], bf[8][2];
#pragma unroll
            for (int mt = 0; mt < 4; mt++) {
                const float* p = Ab + (mt * 16 + g) * GS + kk + 2 * t;
                float2 L0 = *(const float2*)p;
                float2 L1 = *(const float2*)(p + 8 * GS);
                af[mt][0] = __float_as_uint(L0.x);
                af[mt][1] = __float_as_uint(L1.x);
                af[mt][2] = __float_as_uint(L0.y);
                af[mt][3] = __float_as_uint(L1.y);
            }
#pragma unroll
            for (int nt = 0; nt < 8; nt++) {
                float2 L = *(const float2*)(Bb + (nt * 8 + g) * GS + kk + 2 * t);
                bf[nt][0] = __float_as_uint(L.x);
                bf[nt][1] = __float_as_uint(L.y);
            }
#pragma unroll
            for (int mt = 0; mt < 4; mt++)
#pragma unroll
                for (int nt = 0; nt < 8; nt++)
                    MMA_TF32(acc[mt][nt], af[mt], bf[nt]);
        }
        __syncthreads();
    }

    // epilogue: C-frag cols (2t, 2t+1); perm8 slots o0 = t<2?4t:4t-7, o1 = o0+2
    const bool perm_out = QKV && (blockIdx.z != 2);
    const int o0 = (t < 2) ? 4 * t : 4 * t - 7;
#pragma unroll
    for (int mt = 0; mt < 4; mt++) {
#pragma unroll
        for (int nt = 0; nt < 8; nt++) {
            const int row = m0 + mw + mt * 16 + g;
            const int grp = n0 + nw + nt * 8;
            if (perm_out) {
                // q,k: tf32-rounded, perm8 d scatter
                C[(size_t)row * N + grp + o0]           = f2tf32(acc[mt][nt][0]);
                C[(size_t)row * N + grp + o0 + 2]       = f2tf32(acc[mt][nt][1]);
                C[(size_t)(row + 8) * N + grp + o0]     = f2tf32(acc[mt][nt][2]);
                C[(size_t)(row + 8) * N + grp + o0 + 2] = f2tf32(acc[mt][nt][3]);
            } else if (QKV) {
                // v: tf32-rounded, normal layout
                *(float2*)&C[(size_t)row * N + grp + 2 * t] =
                    make_float2(f2tf32(acc[mt][nt][0]), f2tf32(acc[mt][nt][1]));
                *(float2*)&C[(size_t)(row + 8) * N + grp + 2 * t] =
                    make_float2(f2tf32(acc[mt][nt][2]), f2tf32(acc[mt][nt][3]));
            } else {
                // final output: full fp32, normal layout
                *(float2*)&C[(size_t)row * N + grp + 2 * t] =
                    make_float2(acc[mt][nt][0], acc[mt][nt][1]);
                *(float2*)&C[(size_t)(row + 8) * N + grp + 2 * t] =
                    make_float2(acc[mt][nt][2], acc[mt][nt][3]);
            }
        }
    }
}

// ---------------------------------------------------------------------------
// tf32 flash attention v4: 256 thr (8 warps x 32 Q-rows), Q tile 256,
// KV tile 64 double-buffered. Q/K gmem are perm8 on d -> frag loads LDS.64.
// Softmax in log2 domain (ex2.approx; 0.125*log2e folded into Q).
// O written perm8 on d (consumed by out-proj with perm8 Wo).
// ---------------------------------------------------------------------------
#define QST 72
#define KST 72
#define VST 72
#define PST 68
#define KBUF (64 * KST)
#define VBUF (64 * VST)
#define QROWS 256
#define FLASH_SMEM ((QROWS * QST + 2 * KBUF + 2 * VBUF + QROWS * PST) * 4)  // 217088

__global__ __launch_bounds__(256)
void flash_tf32(const float* __restrict__ Q, const float* __restrict__ K,
                const float* __restrict__ V, float* __restrict__ O)
{
    extern __shared__ float sm[];
    float* Qs  = sm;                       // [256][QST]
    float* Ksm = Qs + QROWS * QST;         // [2][64][KST]
    float* Vsm = Ksm + 2 * KBUF;           // [2][64][VST]
    float* Psm = Vsm + 2 * VBUF;           // [256][PST]

    const int tid  = threadIdx.x;
    const int lane = tid & 31;
    const int warp = tid >> 5;
    const int g    = lane >> 2;
    const int t    = lane & 3;
    const int q0   = blockIdx.x * QROWS;
    const int h    = blockIdx.y;
    const int b    = blockIdx.z;
    const size_t base = (size_t)b * TLEN * DM + (size_t)h * DHD;

    const int lr = tid >> 4;               // 0..15
    const int lc = (tid & 15) << 2;        // 0..60

    // Q tile (perm8 already in gmem); fold 0.125*log2e, re-round to tf32
    const float QSC = 0.125f * 1.44269504088896340736f;
#pragma unroll
    for (int i = 0; i < 16; i++) {
        const int row = lr + 16 * i;
        float4 v = *(const float4*)(Q + base + (size_t)(q0 + row) * DM + lc);
        v.x = f2tf32(v.x * QSC); v.y = f2tf32(v.y * QSC);
        v.z = f2tf32(v.z * QSC); v.w = f2tf32(v.w * QSC);
        *(float4*)&Qs[row * QST + lc] = v;
    }

    const int mw = warp * 32;

    float of[2][8][4];
#pragma unroll
    for (int mt = 0; mt < 2; mt++)
#pragma unroll
        for (int nt = 0; nt < 8; nt++)
#pragma unroll
            for (int r = 0; r < 4; r++) of[mt][nt][r] = 0.0f;

    float m_run[2][2] = {{-1e30f, -1e30f}, {-1e30f, -1e30f}};
    float l_run[2][2] = {{0.0f, 0.0f}, {0.0f, 0.0f}};

    const uint32_t sK = (uint32_t)__cvta_generic_to_shared(Ksm);
    const uint32_t sV = (uint32_t)__cvta_generic_to_shared(Vsm);

#pragma unroll
    for (int i = 0; i < 4; i++) {
        const int row = lr + 16 * i;
        cp16(sK + (uint32_t)(row * KST + lc) * 4u, K + base + (size_t)row * DM + lc);
        cp16(sV + (uint32_t)(row * VST + lc) * 4u, V + base + (size_t)row * DM + lc);
    }
    CP_COMMIT();

    const int NT = TLEN / 64;
    for (int tk = 0; tk < NT; tk++) {
        const int cur = tk & 1;
        __syncthreads();
        if (tk + 1 < NT) {
            const int kv1 = (tk + 1) * 64;
            const uint32_t ko = (uint32_t)((cur ^ 1) * KBUF) * 4u;
            const uint32_t vo = (uint32_t)((cur ^ 1) * VBUF) * 4u;
#pragma unroll
            for (int i = 0; i < 4; i++) {
                const int row = lr + 16 * i;
                cp16(sK + ko + (uint32_t)(row * KST + lc) * 4u,
                     K + base + (size_t)(kv1 + row) * DM + lc);
                cp16(sV + vo + (uint32_t)(row * VST + lc) * 4u,
                     V + base + (size_t)(kv1 + row) * DM + lc);
            }
            CP_COMMIT();
            CP_WAIT1();
        } else {
            CP_WAIT0();
        }
        __syncthreads();

        const float* Kb = Ksm + cur * KBUF;
        const float* Vb = Vsm + cur * VBUF;

        // ---- S = Q K^T (log2-scaled) ----
        float sf[2][8][4];
#pragma unroll
        for (int mt = 0; mt < 2; mt++)
#pragma unroll
            for (int nt = 0; nt < 8; nt++)
#pragma unroll
                for (int r = 0; r < 4; r++) sf[mt][nt][r] = 0.0f;

#pragma unroll
        for (int kc = 0; kc < 8; kc++) {
            const int kk = kc * 8;
            uint32_t qf[2][4], kb[8][2];
#pragma unroll
            for (int mt = 0; mt < 2; mt++) {
                const float* p = Qs + (mw + mt * 16 + g) * QST + kk + 2 * t;
                float2 L0 = *(const float2*)p;
                float2 L1 = *(const float2*)(p + 8 * QST);
                qf[mt][0] = __float_as_uint(L0.x);
                qf[mt][1] = __float_as_uint(L1.x);
                qf[mt][2] = __float_as_uint(L0.y);
                qf[mt][3] = __float_as_uint(L1.y);
            }
#pragma unroll
            for (int nt = 0; nt < 8; nt++) {
                float2 L = *(const float2*)(Kb + (nt * 8 + g) * KST + kk + 2 * t);
                kb[nt][0] = __float_as_uint(L.x);
                kb[nt][1] = __float_as_uint(L.y);
            }
#pragma unroll
            for (int mt = 0; mt < 2; mt++)
#pragma unroll
                for (int nt = 0; nt < 8; nt++)
                    MMA_TF32(sf[mt][nt], qf[mt], kb[nt]);
        }

        // ---- online softmax (base-2) ----
#pragma unroll
        for (int mt = 0; mt < 2; mt++) {
#pragma unroll
            for (int rh = 0; rh < 2; rh++) {
                float mx = -1e30f;
#pragma unroll
                for (int nt = 0; nt < 8; nt++)
                    mx = fmaxf(mx, fmaxf(sf[mt][nt][rh * 2], sf[mt][nt][rh * 2 + 1]));
                mx = fmaxf(mx, __shfl_xor_sync(0xffffffffu, mx, 1));
                mx = fmaxf(mx, __shfl_xor_sync(0xffffffffu, mx, 2));
                const float newm = fmaxf(m_run[mt][rh], mx);
                const float fac  = ex2(m_run[mt][rh] - newm);
                float sum = 0.0f;
                float* prow = Psm + (mw + mt * 16 + rh * 8 + g) * PST + 2 * t;
#pragma unroll
                for (int nt = 0; nt < 8; nt++) {
                    const float p0 = ex2(sf[mt][nt][rh * 2]     - newm);
                    const float p1 = ex2(sf[mt][nt][rh * 2 + 1] - newm);
                    sum += p0 + p1;
                    *(float2*)&prow[nt * 8] = make_float2(f2tf32(p0), f2tf32(p1));
                }
                sum += __shfl_xor_sync(0xffffffffu, sum, 1);
                sum += __shfl_xor_sync(0xffffffffu, sum, 2);
                l_run[mt][rh] = l_run[mt][rh] * fac + sum;
                m_run[mt][rh] = newm;
#pragma unroll
                for (int nt = 0; nt < 8; nt++) {
                    of[mt][nt][rh * 2]     *= fac;
                    of[mt][nt][rh * 2 + 1] *= fac;
                }
            }
        }
        __syncwarp();   // P rows warp-private

        // ---- O += P V (P unpermuted; scalar A-frags, scalar V B-frags) ----
#pragma unroll
        for (int kc = 0; kc < 8; kc++) {
            const int kk = kc * 8;
            uint32_t pf[2][4], vb[8][2];
#pragma unroll
            for (int mt = 0; mt < 2; mt++) {
                const float* p = Psm + (mw + mt * 16 + g) * PST + kk + t;
                pf[mt][0] = __float_as_uint(p[0]);
                pf[mt][1] = __float_as_uint(p[8 * PST]);
                pf[mt][2] = __float_as_uint(p[4]);
                pf[mt][3] = __float_as_uint(p[8 * PST + 4]);
            }
#pragma unroll
            for (int nt = 0; nt < 8; nt++) {
                const float* p = Vb + (kk + t) * VST + nt * 8 + g;
                vb[nt][0] = __float_as_uint(p[0]);
                vb[nt][1] = __float_as_uint(p[4 * VST]);
            }
#pragma unroll
            for (int mt = 0; mt < 2; mt++)
#pragma unroll
                for (int nt = 0; nt < 8; nt++)
                    MMA_TF32(of[mt][nt], pf[mt], vb[nt]);
        }
    }

    // ---- epilogue: normalize, write perm8 d (batch offset via base) ----
    const int o0 = (t < 2) ? 4 * t : 4 * t - 7;
#pragma unroll
    for (int mt = 0; mt < 2; mt++) {
#pragma unroll
        for (int rh = 0; rh < 2; rh++) {
            const float inv = 1.0f / l_run[mt][rh];
            const int rloc = q0 + mw + mt * 16 + rh * 8 + g;
            float* Op = O + base + (size_t)rloc * DM;
#pragma unroll
            for (int nt = 0; nt < 8; nt++) {
                Op[nt * 8 + o0]     = f2tf32(of[mt][nt][rh * 2] * inv);
                Op[nt * 8 + o0 + 2] = f2tf32(of[mt][nt][rh * 2 + 1] * inv);
            }
        }
    }
}

// ---------------------------------------------------------------------------
// Launch
// ---------------------------------------------------------------------------
extern "C" void kernel_launch(void* const* d_in, const int* in_sizes, int n_in,
                              void* d_out, int out_size)
{
    (void)in_sizes; (void)n_in; (void)out_size;
    const float* x  = (const float*)d_in[0];
    const float* Wq = (const float*)d_in[1];
    const float* Wk = (const float*)d_in[2];
    const float* Wv = (const float*)d_in[3];
    const float* Wo = (const float*)d_in[4];
    float* out = (float*)d_out;

    float *q, *k, *v, *ot, *xc, *wq, *wk, *wv, *wo;
    cudaGetSymbolAddress((void**)&q,  g_q);
    cudaGetSymbolAddress((void**)&k,  g_k);
    cudaGetSymbolAddress((void**)&v,  g_v);
    cudaGetSymbolAddress((void**)&ot, g_ot);
    cudaGetSymbolAddress((void**)&xc, g_xc);
    cudaGetSymbolAddress((void**)&wq, g_wq);
    cudaGetSymbolAddress((void**)&wk, g_wk);
    cudaGetSymbolAddress((void**)&wv, g_wv);
    cudaGetSymbolAddress((void**)&wo, g_wo);

    cudaFuncSetAttribute(gemm_tf32<true>,
                         cudaFuncAttributeMaxDynamicSharedMemorySize, GEMM_SMEM);
    cudaFuncSetAttribute(gemm_tf32<false>,
                         cudaFuncAttributeMaxDynamicSharedMemorySize, GEMM_SMEM);
    cudaFuncSetAttribute(flash_tf32,
                         cudaFuncAttributeMaxDynamicSharedMemorySize, FLASH_SMEM);
    cudaFuncSetAttribute(gemm_tf32<true>,
                         cudaFuncAttributePreferredSharedMemoryCarveout, 100);
    cudaFuncSetAttribute(gemm_tf32<false>,
                         cudaFuncAttributePreferredSharedMemoryCarveout, 100);
    cudaFuncSetAttribute(flash_tf32,
                         cudaFuncAttributePreferredSharedMemoryCarveout, 100);

    // tf32-round + perm8 the contraction dims
    cvt_x<<<(BT * DM / 8 + 255) / 256, 256>>>((const float4*)x, (float4*)xc, BT * DM / 8);
    {
        dim3 gw((DM * DM / 8 + 255) / 256, 1, 4);
        cvt_w4<<<gw, 256>>>((const float4*)Wq, (float4*)wq,
                            (const float4*)Wk, (float4*)wk,
                            (const float4*)Wv, (float4*)wv,
                            (const float4*)Wo, (float4*)wo,
                            DM * DM / 8);
    }

    // fused QKV projection (q,k written perm8 d; v normal)
    dim3 gq(DM / 256, BT / 128, 3);
    gemm_tf32<true><<<gq, 256, GEMM_SMEM>>>(xc, wq, wk, wv, q, k, v, BT, DM, DM);

    // flash attention (O written perm8 d)
    flash_tf32<<<dim3(TLEN / QROWS, NH, BATCH), 256, FLASH_SMEM>>>(q, k, v, ot);

    // output projection (ot perm8 x wo perm8 -> normal out)
    dim3 gg(DM / 256, BT / 128, 1);
    gemm_tf32<false><<<gg, 256, GEMM_SMEM>>>(ot, wo, nullptr, nullptr, out, nullptr, nullptr, BT, DM, DM);
}